// round 14
// baseline (speedup 1.0000x reference)
#include <cuda_runtime.h>
#include <math.h>
#include <stdint.h>

// Problem constants
#define BB 32
#define SS 4096
#define HH 1024
#define NSPLIT 16                 // splits of S per batch -> 512 blocks
#define S_SPLIT (SS / NSPLIT)     // 256 rows per block
#define CHUNK 8                   // rows per tile
#define NCHUNK (S_SPLIT / CHUNK)  // 32 tiles per block
#define TPB 256                   // threads; each owns 4 h-cols (float4)
#define F4_PER_B (HH / 4)         // 256
#define NSTAGE 3
#define TILE_BYTES (CHUNK * HH * 4)           // 32768
#define SMEM_DYN (NSTAGE * TILE_BYTES + 2 * CHUNK * TPB * 4)  // 98304+16384=114688

// Scratch for split-K partials (no runtime allocation allowed).
// energy = tanh(.) in [-1,1] => exp(energy) in [1/e, e]: no max-subtraction
// needed; softmax(e) == exp(e)/sum(exp(e)) exactly.
__device__ float g_cpart[BB * NSPLIT * HH];   // 2 MiB partial contexts
__device__ float g_l[BB * NSPLIT];            // partial normalizers
__device__ unsigned int g_ticket[BB];         // zero-init; last block resets

static __device__ __forceinline__ uint32_t smem_u32(const void* p) {
    uint32_t a;
    asm("{ .reg .u64 t; cvta.to.shared.u64 t, %1; cvt.u32.u64 %0, t; }"
        : "=r"(a) : "l"(p));
    return a;
}

static __device__ __forceinline__ void mbar_init(uint32_t mbar, uint32_t cnt) {
    asm volatile("mbarrier.init.shared.b64 [%0], %1;" :: "r"(mbar), "r"(cnt) : "memory");
}
static __device__ __forceinline__ void mbar_expect_tx(uint32_t mbar, uint32_t bytes) {
    asm volatile("mbarrier.arrive.expect_tx.shared.b64 _, [%0], %1;"
                 :: "r"(mbar), "r"(bytes) : "memory");
}
static __device__ __forceinline__ void bulk_g2s(uint32_t dst, const void* src,
                                                uint32_t bytes, uint32_t mbar) {
    asm volatile("cp.async.bulk.shared::cluster.global.mbarrier::complete_tx::bytes "
                 "[%0], [%1], %2, [%3];"
                 :: "r"(dst), "l"(src), "r"(bytes), "r"(mbar) : "memory");
}
static __device__ __forceinline__ void mbar_wait(uint32_t mbar, uint32_t parity) {
    uint32_t done;
    asm volatile("{\n\t.reg .pred p;\n\t"
                 "mbarrier.try_wait.parity.acquire.cta.shared::cta.b64 p, [%1], %2;\n\t"
                 "selp.b32 %0, 1, 0, p;\n\t}"
                 : "=r"(done) : "r"(mbar), "r"(parity) : "memory");
    while (!done) {
        asm volatile("{\n\t.reg .pred p;\n\t"
                     "mbarrier.try_wait.parity.acquire.cta.shared::cta.b64 p, [%1], %2;\n\t"
                     "selp.b32 %0, 1, 0, p;\n\t}"
                     : "=r"(done) : "r"(mbar), "r"(parity) : "memory");
    }
}

__global__ __launch_bounds__(TPB)
void attn_fused(const float* __restrict__ x, const float* __restrict__ w,
                float* __restrict__ out) {
    extern __shared__ char dyn[];
    float* tiles = (float*)dyn;                               // NSTAGE tiles
    float* sred  = (float*)(dyn + NSTAGE * TILE_BYTES);       // [2][CHUNK*TPB]
    __shared__ float sp_sh[2][CHUNK];
    __shared__ unsigned int s_islast;
    __shared__ __align__(8) unsigned long long mbar_store[NSTAGE];

    const int blk = blockIdx.x;
    const int b   = blk / NSPLIT;
    const int sp  = blk % NSPLIT;
    const int t   = threadIdx.x;
    const int wid = t >> 5;
    const int lane = t & 31;

    uint32_t mb[NSTAGE];
    #pragma unroll
    for (int s = 0; s < NSTAGE; s++) mb[s] = smem_u32(&mbar_store[s]);

    if (t == 0) {
        #pragma unroll
        for (int s = 0; s < NSTAGE; s++) mbar_init(mb[s], 1);
    }
    __syncthreads();

    const char* xsrc =
        (const char*)(x + ((size_t)b * SS + (size_t)sp * S_SPLIT) * HH);

    // Prologue: fill the pipeline (3 tiles in flight).
    if (t == 0) {
        #pragma unroll
        for (int s = 0; s < NSTAGE; s++) {
            mbar_expect_tx(mb[s], TILE_BYTES);
            bulk_g2s(smem_u32(tiles) + s * TILE_BYTES,
                     xsrc + (size_t)s * TILE_BYTES, TILE_BYTES, mb[s]);
        }
    }

    const float4 w4 = ((const float4*)w)[t];
    float4 c = make_float4(0.f, 0.f, 0.f, 0.f);
    float l = 0.f;

    for (int ch = 0; ch < NCHUNK; ch++) {
        const int st = ch % NSTAGE;
        const uint32_t par = (uint32_t)((ch / NSTAGE) & 1);
        const int pb = ch & 1;

        mbar_wait(mb[st], par);

        // Tile smem -> registers (conflict-free LDS.128), tile consumed here.
        const float4* tp = (const float4*)(dyn + (size_t)st * TILE_BYTES);
        float4 xr[CHUNK];
        #pragma unroll
        for (int r = 0; r < CHUNK; r++) xr[r] = tp[r * (HH / 4) + t];

        #pragma unroll
        for (int r = 0; r < CHUNK; r++) {
            sred[pb * (CHUNK * TPB) + r * TPB + t] =
                xr[r].x * w4.x + xr[r].y * w4.y + xr[r].z * w4.z + xr[r].w * w4.w;
        }
        __syncthreads();   // all threads past tile reads AND sred published

        // Refill this stage for tile ch+3 — overlaps reduce/exp/accumulate.
        if (t == 0 && ch + NSTAGE < NCHUNK) {
            mbar_expect_tx(mb[st], TILE_BYTES);
            bulk_g2s(smem_u32(tiles) + st * TILE_BYTES,
                     xsrc + (size_t)(ch + NSTAGE) * TILE_BYTES, TILE_BYTES, mb[st]);
        }

        // warp `wid` reduces row `wid`; lane 0 -> p = exp(tanh(s)).
        {
            const float* rowp = &sred[pb * (CHUNK * TPB) + wid * TPB];
            float s = rowp[lane] + rowp[lane + 32] + rowp[lane + 64] + rowp[lane + 96]
                    + rowp[lane + 128] + rowp[lane + 160] + rowp[lane + 192] + rowp[lane + 224];
            #pragma unroll
            for (int off = 16; off > 0; off >>= 1)
                s += __shfl_xor_sync(0xffffffffu, s, off);
            if (lane == 0) sp_sh[pb][wid] = expf(tanhf(s));
        }
        __syncthreads();

        // Accumulate (sred parity double-buffered: no trailing barrier).
        #pragma unroll
        for (int r = 0; r < CHUNK; r++) {
            const float p = sp_sh[pb][r];
            l   += p;
            c.x += p * xr[r].x;
            c.y += p * xr[r].y;
            c.z += p * xr[r].z;
            c.w += p * xr[r].w;
        }
    }

    // Publish this split's partial.
    const int pidx = b * NSPLIT + sp;
    ((float4*)g_cpart)[(size_t)pidx * F4_PER_B + t] = c;
    if (t == 0) g_l[pidx] = l;

    __threadfence();
    if (t == 0) {
        const unsigned int prev = atomicAdd(&g_ticket[b], 1u);
        s_islast = (prev == NSPLIT - 1) ? 1u : 0u;
    }
    __syncthreads();
    if (s_islast == 0) return;

    // ---- Last block of batch b: combine 16 L2-hot partials (fixed order) ----
    __threadfence();

    float L = 0.f;
    #pragma unroll
    for (int p = 0; p < NSPLIT; p++) L += g_l[b * NSPLIT + p];

    float4 acc = make_float4(0.f, 0.f, 0.f, 0.f);
    #pragma unroll
    for (int p = 0; p < NSPLIT; p++) {
        const float4 cp =
            ((const float4*)g_cpart)[(size_t)(b * NSPLIT + p) * F4_PER_B + t];
        acc.x += cp.x; acc.y += cp.y; acc.z += cp.z; acc.w += cp.w;
    }
    const float inv = 1.f / L;
    acc.x *= inv; acc.y *= inv; acc.z *= inv; acc.w *= inv;
    ((float4*)out)[(size_t)b * F4_PER_B + t] = acc;

    if (t == 0) g_ticket[b] = 0u;
}

extern "C" void kernel_launch(void* const* d_in, const int* in_sizes, int n_in,
                              void* d_out, int out_size) {
    const float* x = (const float*)d_in[0];   // [B, S, H] fp32
    const float* w = (const float*)d_in[1];   // [H] fp32
    float* out = (float*)d_out;               // [B, H] fp32
    (void)in_sizes; (void)n_in; (void)out_size;

    cudaFuncSetAttribute(attn_fused,
                         cudaFuncAttributeMaxDynamicSharedMemorySize, SMEM_DYN);
    attn_fused<<<BB * NSPLIT, TPB, SMEM_DYN>>>(x, w, out);
}

// round 15
// speedup vs baseline: 1.0033x; 1.0033x over previous
#include <cuda_runtime.h>
#include <math.h>

// Problem constants
#define BB 32
#define SS 4096
#define HH 1024
#define NSPLIT 16                 // splits of S per batch -> 512 blocks
#define S_SPLIT (SS / NSPLIT)     // 256 rows per block
#define CHUNK 8                   // rows per chunk
#define NCHUNK (S_SPLIT / CHUNK)  // 32 (even -> clean unroll by 2)
#define TPB 256                   // threads; each owns 4 h-cols (float4)
#define F4_PER_B (HH / 4)         // 256

// Scratch for split-K partials (no runtime allocation allowed).
// energy = tanh(.) in [-1,1] => exp(energy) in [1/e, e]: no max-subtraction
// needed; softmax(e) == exp(e)/sum(exp(e)) exactly.
__device__ float g_cpart[BB * NSPLIT * HH];   // 2 MiB partial contexts
__device__ float g_l[BB * NSPLIT];            // partial normalizers
__device__ unsigned int g_ticket[BB];         // zero-init; last block resets

__global__ __launch_bounds__(TPB)
void attn_fused(const float* __restrict__ x, const float* __restrict__ w,
                float* __restrict__ out) {
    const int blk = blockIdx.x;
    const int b   = blk / NSPLIT;
    const int sp  = blk % NSPLIT;
    const int t   = threadIdx.x;
    const int wid = t >> 5;
    const int lane = t & 31;

    const float4* __restrict__ x4 =
        (const float4*)(x + ((size_t)b * SS + (size_t)sp * S_SPLIT) * HH);

    const float4 w4 = ((const float4*)w)[t];

    // Parity double-buffered smem (no trailing WAR barrier needed).
    __shared__ float sred[2][CHUNK * TPB];   // 16 KiB
    __shared__ float sp_sh[2][CHUNK];
    __shared__ unsigned int s_islast;

    float4 c = make_float4(0.f, 0.f, 0.f, 0.f);
    float l = 0.f;

    // Two statically-named register tiles (NO dynamic indexing -> no spills).
    float4 xa[CHUNK], xb[CHUNK];

    // Preload chunk 0 into xa.
    #pragma unroll
    for (int r = 0; r < CHUNK; r++)
        xa[r] = __ldcs(&x4[(size_t)r * (HH / 4) + t]);

    #pragma unroll 1
    for (int ch = 0; ch < NCHUNK; ch += 2) {
        // ---------- even chunk (xa), parity buffer 0 ----------
        #pragma unroll
        for (int r = 0; r < CHUNK; r++) {
            sred[0][r * TPB + t] = xa[r].x * w4.x + xa[r].y * w4.y
                                 + xa[r].z * w4.z + xa[r].w * w4.w;
        }
        __syncthreads();

        // Issue odd chunk's loads NOW — they fly over reduce/exp/accumulate.
        {
            const int row0 = (ch + 1) * CHUNK;
            #pragma unroll
            for (int r = 0; r < CHUNK; r++)
                xb[r] = __ldcs(&x4[(size_t)(row0 + r) * (HH / 4) + t]);
        }

        {
            const float* rowp = &sred[0][wid * TPB];
            float s = rowp[lane] + rowp[lane + 32] + rowp[lane + 64] + rowp[lane + 96]
                    + rowp[lane + 128] + rowp[lane + 160] + rowp[lane + 192] + rowp[lane + 224];
            #pragma unroll
            for (int off = 16; off > 0; off >>= 1)
                s += __shfl_xor_sync(0xffffffffu, s, off);
            if (lane == 0) sp_sh[0][wid] = expf(tanhf(s));
        }
        __syncthreads();

        #pragma unroll
        for (int r = 0; r < CHUNK; r++) {
            const float p = sp_sh[0][r];
            l   += p;
            c.x += p * xa[r].x;
            c.y += p * xa[r].y;
            c.z += p * xa[r].z;
            c.w += p * xa[r].w;
        }

        // ---------- odd chunk (xb), parity buffer 1 ----------
        #pragma unroll
        for (int r = 0; r < CHUNK; r++) {
            sred[1][r * TPB + t] = xb[r].x * w4.x + xb[r].y * w4.y
                                 + xb[r].z * w4.z + xb[r].w * w4.w;
        }
        __syncthreads();

        // Issue next even chunk's loads (if any) — overlap xb's reduce phase.
        if (ch + 2 < NCHUNK) {
            const int row0 = (ch + 2) * CHUNK;
            #pragma unroll
            for (int r = 0; r < CHUNK; r++)
                xa[r] = __ldcs(&x4[(size_t)(row0 + r) * (HH / 4) + t]);
        }

        {
            const float* rowp = &sred[1][wid * TPB];
            float s = rowp[lane] + rowp[lane + 32] + rowp[lane + 64] + rowp[lane + 96]
                    + rowp[lane + 128] + rowp[lane + 160] + rowp[lane + 192] + rowp[lane + 224];
            #pragma unroll
            for (int off = 16; off > 0; off >>= 1)
                s += __shfl_xor_sync(0xffffffffu, s, off);
            if (lane == 0) sp_sh[1][wid] = expf(tanhf(s));
        }
        __syncthreads();

        #pragma unroll
        for (int r = 0; r < CHUNK; r++) {
            const float p = sp_sh[1][r];
            l   += p;
            c.x += p * xb[r].x;
            c.y += p * xb[r].y;
            c.z += p * xb[r].z;
            c.w += p * xb[r].w;
        }
    }

    // Publish this split's partial.
    const int pidx = b * NSPLIT + sp;
    ((float4*)g_cpart)[(size_t)pidx * F4_PER_B + t] = c;
    if (t == 0) g_l[pidx] = l;

    // Release partials, then take a ticket for this batch.
    __threadfence();
    if (t == 0) {
        const unsigned int prev = atomicAdd(&g_ticket[b], 1u);
        s_islast = (prev == NSPLIT - 1) ? 1u : 0u;
    }
    __syncthreads();
    if (s_islast == 0) return;

    // ---- Last block of batch b: combine 16 L2-hot partials (fixed order) ----
    __threadfence();

    float L = 0.f;
    #pragma unroll
    for (int p = 0; p < NSPLIT; p++) L += g_l[b * NSPLIT + p];

    float4 acc = make_float4(0.f, 0.f, 0.f, 0.f);
    #pragma unroll
    for (int p = 0; p < NSPLIT; p++) {
        const float4 cp =
            ((const float4*)g_cpart)[(size_t)(b * NSPLIT + p) * F4_PER_B + t];
        acc.x += cp.x; acc.y += cp.y; acc.z += cp.z; acc.w += cp.w;
    }
    const float inv = 1.f / L;
    acc.x *= inv; acc.y *= inv; acc.z *= inv; acc.w *= inv;
    ((float4*)out)[(size_t)b * F4_PER_B + t] = acc;

    // Reset ticket for the next graph replay.
    if (t == 0) g_ticket[b] = 0u;
}

extern "C" void kernel_launch(void* const* d_in, const int* in_sizes, int n_in,
                              void* d_out, int out_size) {
    const float* x = (const float*)d_in[0];   // [B, S, H] fp32
    const float* w = (const float*)d_in[1];   // [H] fp32
    float* out = (float*)d_out;               // [B, H] fp32
    (void)in_sizes; (void)n_in; (void)out_size;

    attn_fused<<<BB * NSPLIT, TPB>>>(x, w, out);
}